// round 2
// baseline (speedup 1.0000x reference)
#include <cuda_runtime.h>
#include <cuda_bf16.h>
#include <mma.h>
#include <cstdint>

using namespace nvcuda;

// Problem constants
#define B_DIM    32
#define S_DIM    2048
#define H_DIM    4096
#define R_DIM    64
#define TILE_M   128
#define KC       32                    // K elements per chunk
#define NCHUNK   (H_DIM / KC)          // 128
#define NTHREADS 256

// SMEM layout: padded row stride to dodge bank conflicts
#define LDX        36                  // floats per x row (32 + 4 pad)
#define LDW        36                  // floats per w row
#define X_STAGE_F  (TILE_M * LDX)      // 4608 floats = 18432 B
#define W_STAGE_F  (R_DIM * LDW)       // 2304 floats = 9216 B
#define STAGE_F    (X_STAGE_F + W_STAGE_F)      // 6912 floats
#define STAGE_B    (STAGE_F * 4)                // 27648 B
#define SMEM_TOTAL (2 * STAGE_B)                // 55296 B

__device__ __forceinline__ uint32_t f32_to_tf32(float f) {
    uint32_t u;
    asm("cvt.rna.tf32.f32 %0, %1;" : "=r"(u) : "f"(f));
    return u;
}

__device__ __forceinline__ uint32_t smem_u32(const void* p) {
    uint32_t r;
    asm("{ .reg .u64 t; cvta.to.shared.u64 t, %1; cvt.u32.u64 %0, t; }"
        : "=r"(r) : "l"(p));
    return r;
}

__device__ __forceinline__ void sts128(uint32_t addr, uint32_t a, uint32_t b,
                                       uint32_t c, uint32_t d) {
    asm volatile("st.shared.v4.b32 [%0], {%1, %2, %3, %4};"
                 :: "r"(addr), "r"(a), "r"(b), "r"(c), "r"(d));
}

__global__ void __launch_bounds__(NTHREADS, 2)
multilora_wmma_kernel(const float* __restrict__ x,
                      const int* __restrict__ adapter_ids,
                      const float* __restrict__ weight,
                      float* __restrict__ out) {
    extern __shared__ __align__(16) float smem[];
    const uint32_t smem_base = smem_u32(smem);

    const int tid = threadIdx.x;
    const int wid = tid >> 5;

    const int mtile = blockIdx.x;       // 0..15
    const int b     = blockIdx.y;       // 0..31
    const int m0    = mtile * TILE_M;
    const int aid   = __ldg(adapter_ids + b);

    // ---- producer mapping: 1536 float4 quads / chunk over 256 threads = 6 each
    // quads [0,1024): x tile (row = i/8, q = i%8); [1024,1536): w tile.
    const float* gptr[6];
    uint32_t sm_off[6];    // byte offset within a stage buffer
    #pragma unroll
    for (int j = 0; j < 6; j++) {
        int i = tid + j * NTHREADS;
        if (i < 1024) {
            int row = i >> 3, q = i & 7;
            gptr[j]  = x + ((size_t)(b * S_DIM + m0 + row)) * H_DIM + q * 4;
            sm_off[j] = (uint32_t)((row * LDX + q * 4) * 4);
        } else {
            int t = i - 1024;
            int row = t >> 3, q = t & 7;
            gptr[j]  = weight + ((size_t)(aid * R_DIM + row)) * H_DIM + q * 4;
            sm_off[j] = (uint32_t)(X_STAGE_F * 4 + (row * LDW + q * 4) * 4);
        }
    }

    // ---- consumer mapping: 8 warps, 32x32 warp tiles (4 along M, 2 along N)
    const int wm = wid >> 1;            // 0..3 -> M block of 32
    const int wn = wid & 1;             // 0..1 -> N block of 32

    wmma::fragment<wmma::accumulator, 16, 16, 8, float> acc[2][2];
    #pragma unroll
    for (int fi = 0; fi < 2; fi++)
        #pragma unroll
        for (int fj = 0; fj < 2; fj++)
            wmma::fill_fragment(acc[fi][fj], 0.0f);

    // ---- register double buffer for global loads
    float4 cur[6], nxt[6];
    #pragma unroll
    for (int j = 0; j < 6; j++)
        cur[j] = *(const float4*)(gptr[j]);

    for (int kc = 0; kc < NCHUNK; kc++) {
        const int s = kc & 1;
        float* xs = smem + s * STAGE_F;
        float* ws = xs + X_STAGE_F;
        const uint32_t sbase = smem_base + s * STAGE_B;

        // prefetch next chunk into registers (hides DRAM latency under compute)
        if (kc + 1 < NCHUNK) {
            #pragma unroll
            for (int j = 0; j < 6; j++)
                nxt[j] = *(const float4*)(gptr[j] + (size_t)(kc + 1) * KC);
        }

        // RNA round to tf32 + store to padded SMEM
        #pragma unroll
        for (int j = 0; j < 6; j++) {
            uint32_t a0 = f32_to_tf32(cur[j].x);
            uint32_t a1 = f32_to_tf32(cur[j].y);
            uint32_t a2 = f32_to_tf32(cur[j].z);
            uint32_t a3 = f32_to_tf32(cur[j].w);
            sts128(sbase + sm_off[j], a0, a1, a2, a3);
        }

        // Single barrier per chunk:
        //  - RAW: all STS(stage s) visible before compute(stage s)
        //  - WAR: compute(stage s^1) of iter kc-1 precedes this barrier in
        //    program order, so the next iter's STS(stage s^1) is safe.
        __syncthreads();

        // compute: 4 k-steps of m16n16k8
        #pragma unroll
        for (int kk = 0; kk < KC; kk += 8) {
            wmma::fragment<wmma::matrix_a, 16, 16, 8, wmma::precision::tf32,
                           wmma::row_major> af[2];
            wmma::fragment<wmma::matrix_b, 16, 16, 8, wmma::precision::tf32,
                           wmma::col_major> bf[2];
            #pragma unroll
            for (int fi = 0; fi < 2; fi++)
                wmma::load_matrix_sync(af[fi],
                    xs + (wm * 32 + fi * 16) * LDX + kk, LDX);
            #pragma unroll
            for (int fj = 0; fj < 2; fj++)
                wmma::load_matrix_sync(bf[fj],
                    ws + (wn * 32 + fj * 16) * LDW + kk, LDW);
            #pragma unroll
            for (int fi = 0; fi < 2; fi++)
                #pragma unroll
                for (int fj = 0; fj < 2; fj++)
                    wmma::mma_sync(acc[fi][fj], af[fi], bf[fj], acc[fi][fj]);
        }

        #pragma unroll
        for (int j = 0; j < 6; j++) cur[j] = nxt[j];
    }

    // ---- epilogue: direct store to gmem, out is [B, S, R] row-major
    float* obase = out + ((size_t)(b * S_DIM + m0 + wm * 32)) * R_DIM + wn * 32;
    #pragma unroll
    for (int fi = 0; fi < 2; fi++)
        #pragma unroll
        for (int fj = 0; fj < 2; fj++)
            wmma::store_matrix_sync(obase + (size_t)fi * 16 * R_DIM + fj * 16,
                                    acc[fi][fj], R_DIM, wmma::mem_row_major);
}

extern "C" void kernel_launch(void* const* d_in, const int* in_sizes, int n_in,
                              void* d_out, int out_size) {
    const float* x   = (const float*)d_in[0];
    const int*   ids = (const int*)d_in[1];
    const float* w   = (const float*)d_in[2];
    float* out = (float*)d_out;

    const int b = in_sizes[1];   // number of requests (32)

    cudaFuncSetAttribute(multilora_wmma_kernel,
                         cudaFuncAttributeMaxDynamicSharedMemorySize, SMEM_TOTAL);

    dim3 grid(S_DIM / TILE_M, b);
    multilora_wmma_kernel<<<grid, NTHREADS, SMEM_TOTAL>>>(x, ids, w, out);
}